// round 3
// baseline (speedup 1.0000x reference)
#include <cuda_runtime.h>
#include <cuda_fp16.h>

#define B_      2048
#define T_      256
#define LD      32
#define WPB     4
#define THREADS 128
#define BLOCKS  128

// shared-memory offsets in 32-bit words
#define OFF_WXIH  0       // 1024 uint2  (half4: Wxi rows l,l+32 x cols k,32+k)
#define OFF_WHHH  2048    // 1024 uint2  (half4: Whh 4 gates)
#define OFF_WL1H  4096    // 1024 uint   (half2)
#define OFF_WL3H  5120    // 640 uint    (half2)
#define OFF_WL2H  5760    // 320 uint    (half2, two k per entry)
#define OFF_WXIA  6080    // 96 float2
#define OFF_BXI   6272    // 32 float2
#define OFF_BL1   6336    // 32 float
#define OFF_BL2   6368    // 32 float
#define OFF_BL3   6400    // 32 float2
#define OFF_STAGE 6464    // 4 warps * 896 floats
#define SMEM_WORDS 10048  // 40192 bytes

// per-warp staging sub-offsets (floats, within 896-float warp slab)
#define ST_HCH 0     // 32 float4  (h of 4 elems)
#define ST_HCC 128   // 32 float4  (c of 4 elems)
#define ST_ZPL 256   // 32 float4
#define ST_ZPH 384   // 32 float4
#define ST_Z1  512   // 32 float4
#define ST_Z2  640   // 32 float4
#define ST_HIN 768   // 32 float4

__device__ __forceinline__ float tanh_fast(float x) {
    float y;
    asm("tanh.approx.f32 %0, %1;" : "=f"(y) : "f"(x));
    return y;
}
__device__ __forceinline__ float sigmoid_fast(float x) {
    return fmaf(0.5f, tanh_fast(0.5f * x), 0.5f);
}
__device__ __forceinline__ unsigned pack_h2(float a, float b) {
    __half2 h = __floats2half2_rn(a, b);
    return *reinterpret_cast<unsigned*>(&h);
}
__device__ __forceinline__ float2 unpack_h2(unsigned u) {
    return __half22float2(*reinterpret_cast<const __half2*>(&u));
}

__global__ void __launch_bounds__(THREADS, 1) ppo_kernel(
    const float* __restrict__ obs,
    const float* __restrict__ h0,
    const float* __restrict__ c0,
    const float* __restrict__ W1,
    const float* __restrict__ b1,
    const float* __restrict__ W_ih,
    const float* __restrict__ W_hh,
    const float* __restrict__ b_ih,
    const float* __restrict__ b_hh,
    const float* __restrict__ W_xi,
    const float* __restrict__ b_xi,
    const float* __restrict__ Wl1,
    const float* __restrict__ bl1,
    const float* __restrict__ Wl2,
    const float* __restrict__ bl2,
    const float* __restrict__ Wl3,
    const float* __restrict__ bl3,
    float* __restrict__ out)
{
    extern __shared__ float sm[];
    const int tid = threadIdx.x;
    const int wp  = tid >> 5;
    const int l   = tid & 31;
    const int gw  = blockIdx.x * WPB + wp;   // 0..511
    const int e0  = gw * 4;

    uint2*    s_WxiH = (uint2*)(sm + OFF_WXIH);
    uint2*    s_WhhH = (uint2*)(sm + OFF_WHHH);
    unsigned* s_Wl1H = (unsigned*)(sm + OFF_WL1H);
    unsigned* s_Wl3H = (unsigned*)(sm + OFF_WL3H);
    unsigned* s_Wl2H = (unsigned*)(sm + OFF_WL2H);
    float2*   s_WxiA = (float2*)(sm + OFF_WXIA);
    float2*   s_bxi  = (float2*)(sm + OFF_BXI);
    float*    s_bl1  =          sm + OFF_BL1;
    float*    s_bl2  =          sm + OFF_BL2;
    float2*   s_bl3  = (float2*)(sm + OFF_BL3);

    float* slab = sm + OFF_STAGE + wp * 896;
    float4* s_hcH = (float4*)(slab + ST_HCH);
    float4* s_hcC = (float4*)(slab + ST_HCC);
    float4* s_zpL = (float4*)(slab + ST_ZPL);
    float4* s_zpH = (float4*)(slab + ST_ZPH);
    float4* s_z1  = (float4*)(slab + ST_Z1);
    float4* s_z2  = (float4*)(slab + ST_Z2);
    float4* s_hin = (float4*)(slab + ST_HIN);

    // ---- stage weights into shared as fp16 (interleaved, lane-indexed) ----
    for (int idx = tid; idx < 1024; idx += THREADS) {
        int k = idx >> 5, j = idx & 31;
        s_WxiH[idx] = make_uint2(
            pack_h2(W_xi[j*67 + k],      W_xi[(j+32)*67 + k]),
            pack_h2(W_xi[j*67 + 32 + k], W_xi[(j+32)*67 + 32 + k]));
        s_WhhH[idx] = make_uint2(
            pack_h2(W_hh[j*32 + k],      W_hh[(j+32)*32 + k]),
            pack_h2(W_hh[(j+64)*32 + k], W_hh[(j+96)*32 + k]));
        float wa = (j < 20) ? Wl1[j*64 + k]      : 0.f;
        float wb = (j < 20) ? Wl1[j*64 + 32 + k] : 0.f;
        s_Wl1H[idx] = pack_h2(wa, wb);
    }
    for (int idx = tid; idx < 640; idx += THREADS) {
        int k = idx >> 5, j = idx & 31;   // k in 0..19
        s_Wl3H[idx] = pack_h2(Wl3[j*20 + k], Wl3[(j+32)*20 + k]);
    }
    for (int idx = tid; idx < 320; idx += THREADS) {
        int k2 = idx >> 5, j = idx & 31;  // k2 in 0..9
        float wa = (j < 20)               ? Wl2[j*20 + 2*k2]     : 0.f;
        float wb = (j < 20 && 2*k2+1 < 20) ? Wl2[j*20 + 2*k2+1] : 0.f;
        s_Wl2H[idx] = pack_h2(wa, wb);
    }
    if (tid < 96) {
        int a = tid >> 5, j = tid & 31;
        s_WxiA[tid] = make_float2(W_xi[j*67 + 64 + a], W_xi[(j+32)*67 + 64 + a]);
    }
    if (tid < 32) {
        s_bxi[tid] = make_float2(b_xi[tid], b_xi[tid + 32]);
        s_bl1[tid] = (tid < 20) ? bl1[tid] : 0.f;
        s_bl2[tid] = (tid < 20) ? bl2[tid] : 0.f;
        s_bl3[tid] = make_float2(bl3[tid], bl3[tid + 32]);
    }

    // ---- per-lane collapsed x-path weights: W_comb = W_ih @ W1 (exact fp32) ----
    float Wc00,Wc01,Wc02,Wc03, Wc10,Wc11,Wc12,Wc13;
    float Wc20,Wc21,Wc22,Wc23, Wc30,Wc31,Wc32,Wc33;
    float bc0, bc1, bc2, bc3;
    {
        float a0,a1,a2,a3,ab;
        #pragma unroll
        for (int g = 0; g < 4; g++) {
            int row = g*32 + l;
            a0 = a1 = a2 = a3 = ab = 0.f;
            for (int m = 0; m < 64; m++) {
                float w = W_ih[row*64 + m];
                a0 += w * W1[m*4 + 0];
                a1 += w * W1[m*4 + 1];
                a2 += w * W1[m*4 + 2];
                a3 += w * W1[m*4 + 3];
                ab += w * b1[m];
            }
            float bb = ab + b_ih[row] + b_hh[row];
            if (g == 0) { Wc00=a0; Wc01=a1; Wc02=a2; Wc03=a3; bc0=bb; }
            if (g == 1) { Wc10=a0; Wc11=a1; Wc12=a2; Wc13=a3; bc1=bb; }
            if (g == 2) { Wc20=a0; Wc21=a1; Wc22=a2; Wc23=a3; bc2=bb; }
            if (g == 3) { Wc30=a0; Wc31=a1; Wc32=a2; Wc33=a3; bc3=bb; }
        }
    }

    // ---- init recurrent state (4 elements per warp) ----
    float h0r = h0[(e0+0)*LD + l], h1r = h0[(e0+1)*LD + l];
    float h2r = h0[(e0+2)*LD + l], h3r = h0[(e0+3)*LD + l];
    float c0r = c0[(e0+0)*LD + l], c1r = c0[(e0+1)*LD + l];
    float c2r = c0[(e0+2)*LD + l], c3r = c0[(e0+3)*LD + l];
    s_hcH[l] = make_float4(h0r, h1r, h2r, h3r);
    s_hcC[l] = make_float4(c0r, c1r, c2r, c3r);
    __syncthreads();

    // obs loading: lane groups of 8; group g serves element e0+g, sub = l&7 (<7 active)
    const int grp = l >> 3;
    const int sub = l & 7;
    const bool act_lane = (sub < 7);
    const float* pobs = obs + (size_t)(e0 + grp) * T_ * 7 + sub;

    float* pout0 = out + (size_t)(e0+0) * T_ * LD + l;
    float* pout1 = out + (size_t)(e0+1) * T_ * LD + l;
    float* pout2 = out + (size_t)(e0+2) * T_ * LD + l;
    float* pout3 = out + (size_t)(e0+3) * T_ * LD + l;
    const unsigned F = 0xffffffffu;

    float v = act_lane ? pobs[0] : 0.f;     // obs for t=0

    for (int t = 0; t < T_; t++) {
        // prefetch obs for t+1 (hidden behind this step's compute)
        float vn = 0.f;
        if (act_lane && t + 1 < T_) vn = pobs[7];
        pobs += 7;

        float ob00=__shfl_sync(F,v,0),  ob01=__shfl_sync(F,v,1);
        float ob02=__shfl_sync(F,v,2),  ob03=__shfl_sync(F,v,3);
        float ts00=__shfl_sync(F,v,4),  ts01=__shfl_sync(F,v,5),  a0f=__shfl_sync(F,v,6);
        float ob10=__shfl_sync(F,v,8),  ob11=__shfl_sync(F,v,9);
        float ob12=__shfl_sync(F,v,10), ob13=__shfl_sync(F,v,11);
        float ts10=__shfl_sync(F,v,12), ts11=__shfl_sync(F,v,13), a1f=__shfl_sync(F,v,14);
        float ob20=__shfl_sync(F,v,16), ob21=__shfl_sync(F,v,17);
        float ob22=__shfl_sync(F,v,18), ob23=__shfl_sync(F,v,19);
        float ts20=__shfl_sync(F,v,20), ts21=__shfl_sync(F,v,21), a2f=__shfl_sync(F,v,22);
        float ob30=__shfl_sync(F,v,24), ob31=__shfl_sync(F,v,25);
        float ob32=__shfl_sync(F,v,26), ob33=__shfl_sync(F,v,27);
        float ts30=__shfl_sync(F,v,28), ts31=__shfl_sync(F,v,29), a3f=__shfl_sync(F,v,30);

        bool cond0 = (ts00 + ts01) != 0.f;
        bool cond1 = (ts10 + ts11) != 0.f;
        bool cond2 = (ts20 + ts21) != 0.f;
        bool cond3 = (ts30 + ts31) != 0.f;

        // x-path gate pre-activations (exact fp32 weights in registers)
        float gi0 = bc0 + Wc00*ob00 + Wc01*ob01 + Wc02*ob02 + Wc03*ob03;
        float gf0 = bc1 + Wc10*ob00 + Wc11*ob01 + Wc12*ob02 + Wc13*ob03;
        float gg0 = bc2 + Wc20*ob00 + Wc21*ob01 + Wc22*ob02 + Wc23*ob03;
        float go0 = bc3 + Wc30*ob00 + Wc31*ob01 + Wc32*ob02 + Wc33*ob03;
        float gi1 = bc0 + Wc00*ob10 + Wc01*ob11 + Wc02*ob12 + Wc03*ob13;
        float gf1 = bc1 + Wc10*ob10 + Wc11*ob11 + Wc12*ob12 + Wc13*ob13;
        float gg1 = bc2 + Wc20*ob10 + Wc21*ob11 + Wc22*ob12 + Wc23*ob13;
        float go1 = bc3 + Wc30*ob10 + Wc31*ob11 + Wc32*ob12 + Wc33*ob13;
        float gi2 = bc0 + Wc00*ob20 + Wc01*ob21 + Wc02*ob22 + Wc03*ob23;
        float gf2 = bc1 + Wc10*ob20 + Wc11*ob21 + Wc12*ob22 + Wc13*ob23;
        float gg2 = bc2 + Wc20*ob20 + Wc21*ob21 + Wc22*ob22 + Wc23*ob23;
        float go2 = bc3 + Wc30*ob20 + Wc31*ob21 + Wc32*ob22 + Wc33*ob23;
        float gi3 = bc0 + Wc00*ob30 + Wc01*ob31 + Wc02*ob32 + Wc03*ob33;
        float gf3 = bc1 + Wc10*ob30 + Wc11*ob31 + Wc12*ob32 + Wc13*ob33;
        float gg3 = bc2 + Wc20*ob30 + Wc21*ob31 + Wc22*ob32 + Wc23*ob33;
        float go3 = bc3 + Wc30*ob30 + Wc31*ob31 + Wc32*ob32 + Wc33*ob33;

        float hin0 = h0r, hin1 = h1r, hin2 = h2r, hin3 = h3r;
        float cin0 = c0r, cin1 = c1r, cin2 = c2r, cin3 = c3r;

        if (cond0 || cond1 || cond2 || cond3) {   // warp-uniform branch
            int a0 = (int)a0f, a1 = (int)a1f, a2 = (int)a2f, a3 = (int)a3f;
            float2 bx = s_bxi[l];
            float2 A0 = s_WxiA[a0*32 + l];
            float2 A1 = s_WxiA[a1*32 + l];
            float2 A2 = s_WxiA[a2*32 + l];
            float2 A3 = s_WxiA[a3*32 + l];
            float zl0 = bx.x + A0.x, zh0 = bx.y + A0.y;
            float zl1 = bx.x + A1.x, zh1 = bx.y + A1.y;
            float zl2 = bx.x + A2.x, zh2 = bx.y + A2.y;
            float zl3 = bx.x + A3.x, zh3 = bx.y + A3.y;
            #pragma unroll
            for (int k = 0; k < 32; k++) {
                float4 hH = s_hcH[k];
                float4 hC = s_hcC[k];
                uint2 wu  = s_WxiH[k*32 + l];
                float2 wab = unpack_h2(wu.x);   // (W[l,k], W[l+32,k])
                float2 wcd = unpack_h2(wu.y);   // (W[l,32+k], W[l+32,32+k])
                zl0 += hH.x*wab.x; zl1 += hH.y*wab.x; zl2 += hH.z*wab.x; zl3 += hH.w*wab.x;
                zh0 += hH.x*wab.y; zh1 += hH.y*wab.y; zh2 += hH.z*wab.y; zh3 += hH.w*wab.y;
                zl0 += hC.x*wcd.x; zl1 += hC.y*wcd.x; zl2 += hC.z*wcd.x; zl3 += hC.w*wcd.x;
                zh0 += hC.x*wcd.y; zh1 += hC.y*wcd.y; zh2 += hC.z*wcd.y; zh3 += hC.w*wcd.y;
            }
            s_zpL[l] = make_float4(zl0, zl1, zl2, zl3);
            s_zpH[l] = make_float4(zh0, zh1, zh2, zh3);
            __syncwarp();

            float bb = s_bl1[l];
            float z10 = bb, z11 = bb, z12 = bb, z13 = bb;
            #pragma unroll
            for (int k = 0; k < 32; k++) {
                float4 zL = s_zpL[k];
                float4 zH = s_zpH[k];
                float2 w  = unpack_h2(s_Wl1H[k*32 + l]);
                z10 += zL.x*w.x; z11 += zL.y*w.x; z12 += zL.z*w.x; z13 += zL.w*w.x;
                z10 += zH.x*w.y; z11 += zH.y*w.y; z12 += zH.z*w.y; z13 += zH.w*w.y;
            }
            z10 = fmaxf(z10, 0.f); z11 = fmaxf(z11, 0.f);
            z12 = fmaxf(z12, 0.f); z13 = fmaxf(z13, 0.f);
            s_z1[l] = make_float4(z10, z11, z12, z13);
            __syncwarp();

            float b2 = s_bl2[l];
            float z20 = b2, z21 = b2, z22 = b2, z23 = b2;
            #pragma unroll
            for (int k2 = 0; k2 < 10; k2++) {
                float4 za = s_z1[2*k2];
                float4 zb = s_z1[2*k2 + 1];
                float2 w  = unpack_h2(s_Wl2H[k2*32 + l]);
                z20 += za.x*w.x; z21 += za.y*w.x; z22 += za.z*w.x; z23 += za.w*w.x;
                z20 += zb.x*w.y; z21 += zb.y*w.y; z22 += zb.z*w.y; z23 += zb.w*w.y;
            }
            z20 = fmaxf(z20, 0.f); z21 = fmaxf(z21, 0.f);
            z22 = fmaxf(z22, 0.f); z23 = fmaxf(z23, 0.f);
            s_z2[l] = make_float4(z20, z21, z22, z23);
            __syncwarp();

            float2 b3 = s_bl3[l];
            float dl0 = b3.x, dl1 = b3.x, dl2 = b3.x, dl3 = b3.x;
            float dh0 = b3.y, dh1 = b3.y, dh2 = b3.y, dh3 = b3.y;
            #pragma unroll
            for (int k = 0; k < 20; k++) {
                float4 zv = s_z2[k];
                float2 w  = unpack_h2(s_Wl3H[k*32 + l]);
                dl0 += zv.x*w.x; dl1 += zv.y*w.x; dl2 += zv.z*w.x; dl3 += zv.w*w.x;
                dh0 += zv.x*w.y; dh1 += zv.y*w.y; dh2 += zv.z*w.y; dh3 += zv.w*w.y;
            }
            float dt0 = ts01 - ts00, dt1 = ts11 - ts10;
            float dt2 = ts21 - ts20, dt3 = ts31 - ts30;
            if (cond0) { hin0 = fmaf(dt0, dl0, zl0); cin0 = fmaf(dt0, dh0, zh0); }
            if (cond1) { hin1 = fmaf(dt1, dl1, zl1); cin1 = fmaf(dt1, dh1, zh1); }
            if (cond2) { hin2 = fmaf(dt2, dl2, zl2); cin2 = fmaf(dt2, dh2, zh2); }
            if (cond3) { hin3 = fmaf(dt3, dl3, zl3); cin3 = fmaf(dt3, dh3, zh3); }
        }

        s_hin[l] = make_float4(hin0, hin1, hin2, hin3);
        __syncwarp();

        // recurrent gates: += h_in @ W_hh^T
        #pragma unroll
        for (int k = 0; k < 32; k++) {
            float4 hv = s_hin[k];
            uint2 wu  = s_WhhH[k*32 + l];
            float2 wif = unpack_h2(wu.x);   // (Wi, Wf)
            float2 wgo = unpack_h2(wu.y);   // (Wg, Wo)
            gi0 += hv.x*wif.x; gf0 += hv.x*wif.y; gg0 += hv.x*wgo.x; go0 += hv.x*wgo.y;
            gi1 += hv.y*wif.x; gf1 += hv.y*wif.y; gg1 += hv.y*wgo.x; go1 += hv.y*wgo.y;
            gi2 += hv.z*wif.x; gf2 += hv.z*wif.y; gg2 += hv.z*wgo.x; go2 += hv.z*wgo.y;
            gi3 += hv.w*wif.x; gf3 += hv.w*wif.y; gg3 += hv.w*wgo.x; go3 += hv.w*wgo.y;
        }

        // pointwise LSTM cell
        float cn0 = sigmoid_fast(gf0)*cin0 + sigmoid_fast(gi0)*tanh_fast(gg0);
        float hn0 = sigmoid_fast(go0)*tanh_fast(cn0);
        float cn1 = sigmoid_fast(gf1)*cin1 + sigmoid_fast(gi1)*tanh_fast(gg1);
        float hn1 = sigmoid_fast(go1)*tanh_fast(cn1);
        float cn2 = sigmoid_fast(gf2)*cin2 + sigmoid_fast(gi2)*tanh_fast(gg2);
        float hn2 = sigmoid_fast(go2)*tanh_fast(cn2);
        float cn3 = sigmoid_fast(gf3)*cin3 + sigmoid_fast(gi3)*tanh_fast(gg3);
        float hn3 = sigmoid_fast(go3)*tanh_fast(cn3);

        pout0[t*LD] = hn0;
        pout1[t*LD] = hn1;
        pout2[t*LD] = hn2;
        pout3[t*LD] = hn3;

        h0r = hn0; h1r = hn1; h2r = hn2; h3r = hn3;
        c0r = cn0; c1r = cn1; c2r = cn2; c3r = cn3;
        __syncwarp();                       // all lanes done reading s_hin/s_hc
        s_hcH[l] = make_float4(h0r, h1r, h2r, h3r);
        s_hcC[l] = make_float4(c0r, c1r, c2r, c3r);
        __syncwarp();

        v = vn;
    }
}

extern "C" void kernel_launch(void* const* d_in, const int* in_sizes, int n_in,
                              void* d_out, int out_size) {
    (void)in_sizes; (void)n_in; (void)out_size;
    cudaFuncSetAttribute(ppo_kernel, cudaFuncAttributeMaxDynamicSharedMemorySize,
                         SMEM_WORDS * sizeof(float));
    ppo_kernel<<<BLOCKS, THREADS, SMEM_WORDS * sizeof(float)>>>(
        (const float*)d_in[0],  // obs
        (const float*)d_in[1],  // h0
        (const float*)d_in[2],  // c0
        (const float*)d_in[3],  // W1
        (const float*)d_in[4],  // b1
        (const float*)d_in[5],  // W_ih
        (const float*)d_in[6],  // W_hh
        (const float*)d_in[7],  // b_ih
        (const float*)d_in[8],  // b_hh
        (const float*)d_in[9],  // W_xi
        (const float*)d_in[10], // b_xi
        (const float*)d_in[11], // Wl1
        (const float*)d_in[12], // bl1
        (const float*)d_in[13], // Wl2
        (const float*)d_in[14], // bl2
        (const float*)d_in[15], // Wl3
        (const float*)d_in[16], // bl3
        (float*)d_out);
}